// round 1
// baseline (speedup 1.0000x reference)
#include <cuda_runtime.h>

// Problem constants
#define T_STEPS 100
#define BATCH   32
#define N_IN    1024
#define N_OUT   512
#define K_TOT   (T_STEPS * BATCH)   // 3200 combined (t,b) rows

#define LR_LTP_F (1e-4f)
#define LR_LTD_F (-1e-4f)
#define DECAY    (0.951229424500714f)   // exp(-1/20) in fp32

// Output layout: [delta_w (512*1024)] [pre_tr (32*1024)] [post_tr (32*512)]
#define DW_OFF   0
#define PRETR_OFF  (N_OUT * N_IN)                 // 524288
#define POSTTR_OFF (PRETR_OFF + BATCH * N_IN)     // 557056

// Scratch: full trace histories (graph-capturable: no allocations)
static __device__ float g_pre_tr [K_TOT * N_IN];    // [k=3200, 1024]  13.1 MB
static __device__ float g_post_tr[K_TOT * N_OUT];   // [k=3200, 512]    6.5 MB

// ---------------------------------------------------------------------------
// Kernel 1: trace scan. Thread owns one (b,n); loops T. Writes full history
// to scratch and the final trace to the output buffer.
// ---------------------------------------------------------------------------
__global__ void trace_kernel(const float* __restrict__ pre_s,
                             const float* __restrict__ post_s,
                             const float* __restrict__ pre_tr0,
                             const float* __restrict__ post_tr0,
                             float* __restrict__ out)
{
    int idx = blockIdx.x * blockDim.x + threadIdx.x;
    if (idx < BATCH * N_IN) {
        float tr = pre_tr0[idx];
        #pragma unroll 5
        for (int t = 0; t < T_STEPS; t++) {
            tr = tr * DECAY + pre_s[t * (BATCH * N_IN) + idx];
            g_pre_tr[t * (BATCH * N_IN) + idx] = tr;
        }
        out[PRETR_OFF + idx] = tr;
    } else {
        int j = idx - BATCH * N_IN;
        if (j < BATCH * N_OUT) {
            float tr = post_tr0[j];
            #pragma unroll 5
            for (int t = 0; t < T_STEPS; t++) {
                tr = tr * DECAY + post_s[t * (BATCH * N_OUT) + j];
                g_post_tr[t * (BATCH * N_OUT) + j] = tr;
            }
            out[POSTTR_OFF + j] = tr;
        }
    }
}

// ---------------------------------------------------------------------------
// Deterministic spike-column compaction into smem index list.
// Block of 256 threads scans spikes[k*stride + col] for k in [0, K_TOT);
// returns count; s_idx[] holds the k's in ascending order (bitwise
// deterministic: ballot/popc prefix, no atomics).
// ---------------------------------------------------------------------------
__device__ __forceinline__ int compact_spikes(const float* __restrict__ spikes,
                                              int stride, int col,
                                              int* s_idx, int* s_wcnt)
{
    const int tid  = threadIdx.x;
    const int warp = tid >> 5;
    const int lane = tid & 31;
    int cnt = 0;
    for (int base = 0; base < K_TOT; base += 256) {
        int k = base + tid;
        bool sp = (k < K_TOT) && (spikes[(long)k * stride + col] > 0.5f);
        unsigned m = __ballot_sync(0xffffffffu, sp);
        if (lane == 0) s_wcnt[warp] = __popc(m);
        __syncthreads();
        int woff = 0, total = 0;
        #pragma unroll
        for (int w = 0; w < 8; w++) {
            int c = s_wcnt[w];
            if (w < warp) woff += c;
            total += c;
        }
        if (sp) s_idx[cnt + woff + __popc(m & ((1u << lane) - 1u))] = k;
        cnt += total;
        __syncthreads();   // also protects s_wcnt reuse + publishes s_idx
    }
    return cnt;
}

// ---------------------------------------------------------------------------
// Kernel 2: LTP. One CTA per output row o. Gather-sum ~160 pre-trace rows
// (4 KB each, L2 resident), then write dw row directly with soft-LTP factor.
// ---------------------------------------------------------------------------
__global__ void __launch_bounds__(256) ltp_kernel(
    const float* __restrict__ post_s,   // [K_TOT, N_OUT]
    const float* __restrict__ W,        // [N_OUT, N_IN]
    float* __restrict__ dw)             // [N_OUT, N_IN]
{
    __shared__ int s_idx[K_TOT];
    __shared__ int s_wcnt[8];
    const int o   = blockIdx.x;
    const int tid = threadIdx.x;

    int cnt = compact_spikes(post_s, N_OUT, o, s_idx, s_wcnt);

    const float4* tr4 = reinterpret_cast<const float4*>(g_pre_tr);
    float4 acc = make_float4(0.f, 0.f, 0.f, 0.f);

    int j = 0;
    for (; j + 4 <= cnt; j += 4) {
        int k0 = s_idx[j+0], k1 = s_idx[j+1], k2 = s_idx[j+2], k3 = s_idx[j+3];
        float4 v0 = tr4[k0 * (N_IN/4) + tid];
        float4 v1 = tr4[k1 * (N_IN/4) + tid];
        float4 v2 = tr4[k2 * (N_IN/4) + tid];
        float4 v3 = tr4[k3 * (N_IN/4) + tid];
        acc.x += (v0.x + v1.x) + (v2.x + v3.x);
        acc.y += (v0.y + v1.y) + (v2.y + v3.y);
        acc.z += (v0.z + v1.z) + (v2.z + v3.z);
        acc.w += (v0.w + v1.w) + (v2.w + v3.w);
    }
    for (; j < cnt; j++) {
        int k = s_idx[j];
        float4 v = tr4[k * (N_IN/4) + tid];
        acc.x += v.x; acc.y += v.y; acc.z += v.z; acc.w += v.w;
    }

    const float s = LR_LTP_F / (float)BATCH;
    float4 w4 = reinterpret_cast<const float4*>(W)[o * (N_IN/4) + tid];
    float4 r;
    r.x = s * (1.f - w4.x) * acc.x;
    r.y = s * (1.f - w4.y) * acc.y;
    r.z = s * (1.f - w4.z) * acc.z;
    r.w = s * (1.f - w4.w) * acc.w;
    reinterpret_cast<float4*>(dw)[o * (N_IN/4) + tid] = r;
}

// ---------------------------------------------------------------------------
// Kernel 3: LTD. One CTA per input column i. Gather-sum ~160 post-trace rows
// (2 KB each), then RMW the dw column with the soft-LTD factor.
// ---------------------------------------------------------------------------
__global__ void __launch_bounds__(256) ltd_kernel(
    const float* __restrict__ pre_s,    // [K_TOT, N_IN]
    const float* __restrict__ W,        // [N_OUT, N_IN]
    float* __restrict__ dw)             // [N_OUT, N_IN]
{
    __shared__ int s_idx[K_TOT];
    __shared__ int s_wcnt[8];
    const int i   = blockIdx.x;
    const int tid = threadIdx.x;

    int cnt = compact_spikes(pre_s, N_IN, i, s_idx, s_wcnt);

    const float2* tr2 = reinterpret_cast<const float2*>(g_post_tr);
    float2 acc = make_float2(0.f, 0.f);

    int j = 0;
    for (; j + 4 <= cnt; j += 4) {
        int k0 = s_idx[j+0], k1 = s_idx[j+1], k2 = s_idx[j+2], k3 = s_idx[j+3];
        float2 v0 = tr2[k0 * (N_OUT/2) + tid];
        float2 v1 = tr2[k1 * (N_OUT/2) + tid];
        float2 v2 = tr2[k2 * (N_OUT/2) + tid];
        float2 v3 = tr2[k3 * (N_OUT/2) + tid];
        acc.x += (v0.x + v1.x) + (v2.x + v3.x);
        acc.y += (v0.y + v1.y) + (v2.y + v3.y);
    }
    for (; j < cnt; j++) {
        int k = s_idx[j];
        float2 v = tr2[k * (N_OUT/2) + tid];
        acc.x += v.x; acc.y += v.y;
    }

    const float c = LR_LTD_F / (float)BATCH;
    int o0 = 2 * tid, o1 = 2 * tid + 1;
    long p0 = (long)o0 * N_IN + i;
    long p1 = (long)o1 * N_IN + i;
    dw[p0] += c * W[p0] * acc.x;
    dw[p1] += c * W[p1] * acc.y;
}

// ---------------------------------------------------------------------------
extern "C" void kernel_launch(void* const* d_in, const int* in_sizes, int n_in,
                              void* d_out, int out_size)
{
    const float* W       = (const float*)d_in[0];   // [512,1024]
    const float* pre_s   = (const float*)d_in[1];   // [100,32,1024]
    const float* post_s  = (const float*)d_in[2];   // [100,32,512]
    const float* pre_tr0 = (const float*)d_in[3];   // [32,1024]
    const float* post_tr0= (const float*)d_in[4];   // [32,512]
    float* out = (float*)d_out;

    (void)in_sizes; (void)n_in; (void)out_size;

    const int n_trace_threads = BATCH * (N_IN + N_OUT);   // 49152
    trace_kernel<<<(n_trace_threads + 255) / 256, 256>>>(
        pre_s, post_s, pre_tr0, post_tr0, out);

    ltp_kernel<<<N_OUT, 256>>>(post_s, W, out + DW_OFF);
    ltd_kernel<<<N_IN,  256>>>(pre_s,  W, out + DW_OFF);
}

// round 2
// speedup vs baseline: 2.0528x; 2.0528x over previous
#include <cuda_runtime.h>
#include <cuda_fp16.h>

// Problem constants
#define T_STEPS 100
#define BATCH   32
#define N_IN    1024
#define N_OUT   512
#define K_TOT   3200                    // T*B combined rows

#define LR_LTP_F (1e-4f)
#define LR_LTD_F (-1e-4f)
#define DECAY    (0.951229424500714f)   // exp(-1/20)

// Output layout: [delta_w (512*1024)] [pre_tr (32*1024)] [post_tr (32*512)]
#define PRETR_OFF  (N_OUT * N_IN)
#define POSTTR_OFF (PRETR_OFF + BATCH * N_IN)

// Compaction: k-range split into 5 chunks of 640; per-column per-chunk segment
#define K_CHUNKS    5
#define K_PER_CHUNK 640
#define SEG_CAP     80                  // mean 32, 80 ≈ +8.7 sigma
#define LIST_CAP    (K_CHUNKS * SEG_CAP)  // 400

// Scratch (graph-capturable: no allocations)
static __device__ __half g_pre_trh [K_TOT * N_IN];   // 6.55 MB  [k][1024]
static __device__ __half g_post_trh[K_TOT * N_OUT];  // 3.28 MB  [k][512]
static __device__ unsigned short g_list_pre [N_IN  * LIST_CAP];
static __device__ unsigned short g_list_post[N_OUT * LIST_CAP];
static __device__ int g_cnt_pre [N_IN  * K_CHUNKS];
static __device__ int g_cnt_post[N_OUT * K_CHUNKS];
static __device__ float g_bt[N_IN * N_OUT];          // BT[i][o] ltd scratch

#define TRACE_CTAS   192   // 49152 cols / 256
#define COMPACT_CTAS 480   // (64 + 32) col-groups * 5 chunks

// ---------------------------------------------------------------------------
// Kernel A (fused): trace scan (CTAs 0..191) + spike compaction (192..671).
// Independent work -> overlaps in one launch.
// ---------------------------------------------------------------------------
__global__ void __launch_bounds__(256) prep_kernel(
    const float* __restrict__ pre_s,    // [3200, 1024]
    const float* __restrict__ post_s,   // [3200, 512]
    const float* __restrict__ pre_tr0,
    const float* __restrict__ post_tr0,
    float* __restrict__ out)
{
    const int bx  = blockIdx.x;
    const int tid = threadIdx.x;

    if (bx < TRACE_CTAS) {
        int idx = bx * 256 + tid;
        if (idx < BATCH * N_IN) {
            float tr = pre_tr0[idx];
            #pragma unroll 10
            for (int t = 0; t < T_STEPS; t++) {
                tr = tr * DECAY + pre_s[t * (BATCH * N_IN) + idx];
                g_pre_trh[t * (BATCH * N_IN) + idx] = __float2half(tr);
            }
            out[PRETR_OFF + idx] = tr;
        } else {
            int j = idx - BATCH * N_IN;
            float tr = post_tr0[j];
            #pragma unroll 10
            for (int t = 0; t < T_STEPS; t++) {
                tr = tr * DECAY + post_s[t * (BATCH * N_OUT) + j];
                g_post_trh[t * (BATCH * N_OUT) + j] = __float2half(tr);
            }
            out[POSTTR_OFF + j] = tr;
        }
        return;
    }

    // ---- Compaction: CTA handles 16 columns x 640 k, via coalesced smem tiles
    __shared__ float s_tile[64][17];
    const int cb    = bx - TRACE_CTAS;
    const int chunk = cb % K_CHUNKS;
    const int grp   = cb / K_CHUNKS;

    const float* src; int stride, colbase;
    unsigned short* list; int* cntarr;
    if (grp < 64) { src = pre_s;  stride = N_IN;  colbase = grp * 16;
                    list = g_list_pre;  cntarr = g_cnt_pre; }
    else          { src = post_s; stride = N_OUT; colbase = (grp - 64) * 16;
                    list = g_list_post; cntarr = g_cnt_post; }

    const int warp = tid >> 5, lane = tid & 31;
    const unsigned lt = (1u << lane) - 1u;
    const int k0 = chunk * K_PER_CHUNK;
    int cnt0 = 0, cnt1 = 0;
    const int c0 = 2 * warp, c1 = 2 * warp + 1;

    for (int tile = 0; tile < K_PER_CHUNK / 64; tile++) {
        #pragma unroll
        for (int r = 0; r < 4; r++) {
            int e  = r * 256 + tid;
            int kk = e >> 4, cc = e & 15;
            s_tile[kk][cc] =
                src[(size_t)(k0 + tile * 64 + kk) * stride + colbase + cc];
        }
        __syncthreads();

        #pragma unroll
        for (int h = 0; h < 2; h++) {
            int kk = h * 32 + lane;
            bool sp = s_tile[kk][c0] > 0.5f;
            unsigned m = __ballot_sync(0xffffffffu, sp);
            if (sp) list[(size_t)(colbase + c0) * LIST_CAP + chunk * SEG_CAP
                         + cnt0 + __popc(m & lt)]
                    = (unsigned short)(k0 + tile * 64 + kk);
            cnt0 += __popc(m);
        }
        #pragma unroll
        for (int h = 0; h < 2; h++) {
            int kk = h * 32 + lane;
            bool sp = s_tile[kk][c1] > 0.5f;
            unsigned m = __ballot_sync(0xffffffffu, sp);
            if (sp) list[(size_t)(colbase + c1) * LIST_CAP + chunk * SEG_CAP
                         + cnt1 + __popc(m & lt)]
                    = (unsigned short)(k0 + tile * 64 + kk);
            cnt1 += __popc(m);
        }
        __syncthreads();
    }
    if (lane == 0) {
        cntarr[(colbase + c0) * K_CHUNKS + chunk] = cnt0;
        cntarr[(colbase + c1) * K_CHUNKS + chunk] = cnt1;
    }
}

// ---------------------------------------------------------------------------
// Kernel B: fused gather. CTAs [0,512): LTP row o -> dw directly.
//           CTAs [512,1536): LTD col i -> BT[i][o] scratch (coalesced).
// ---------------------------------------------------------------------------
__device__ __forceinline__ void acc4h(uint2 v, float& a0, float& a1,
                                      float& a2, float& a3)
{
    __half2 h0 = *reinterpret_cast<__half2*>(&v.x);
    __half2 h1 = *reinterpret_cast<__half2*>(&v.y);
    float2 f0 = __half22float2(h0);
    float2 f1 = __half22float2(h1);
    a0 += f0.x; a1 += f0.y; a2 += f1.x; a3 += f1.y;
}

__global__ void __launch_bounds__(256) gather_kernel(
    const float* __restrict__ W, float* __restrict__ dw)
{
    __shared__ unsigned short s_idx[LIST_CAP];
    __shared__ int s_pref[K_CHUNKS + 1];
    const int tid = threadIdx.x;
    const bool is_ltp = blockIdx.x < N_OUT;
    const int col = is_ltp ? blockIdx.x : blockIdx.x - N_OUT;
    const int* cntarr = is_ltp ? g_cnt_post : g_cnt_pre;
    const unsigned short* list = is_ltp ? g_list_post : g_list_pre;

    if (tid == 0) {
        int p = 0;
        #pragma unroll
        for (int c = 0; c < K_CHUNKS; c++) {
            s_pref[c] = p; p += cntarr[col * K_CHUNKS + c];
        }
        s_pref[K_CHUNKS] = p;
    }
    __syncthreads();
    for (int slot = tid; slot < LIST_CAP; slot += 256) {
        int c = slot / SEG_CAP, j = slot % SEG_CAP;
        int base = s_pref[c];
        if (base + j < s_pref[c + 1])
            s_idx[base + j] = list[(size_t)col * LIST_CAP + c * SEG_CAP + j];
    }
    __syncthreads();
    const int cnt = s_pref[K_CHUNKS];

    if (is_ltp) {
        // rows of g_pre_trh: 1024 halves = 256 uint2; thread covers cols 4t..4t+3
        const uint2* tr = reinterpret_cast<const uint2*>(g_pre_trh);
        float a0 = 0.f, a1 = 0.f, a2 = 0.f, a3 = 0.f;
        int j = 0;
        for (; j + 4 <= cnt; j += 4) {
            uint2 v0 = tr[(int)s_idx[j + 0] * 256 + tid];
            uint2 v1 = tr[(int)s_idx[j + 1] * 256 + tid];
            uint2 v2 = tr[(int)s_idx[j + 2] * 256 + tid];
            uint2 v3 = tr[(int)s_idx[j + 3] * 256 + tid];
            acc4h(v0, a0, a1, a2, a3);
            acc4h(v1, a0, a1, a2, a3);
            acc4h(v2, a0, a1, a2, a3);
            acc4h(v3, a0, a1, a2, a3);
        }
        for (; j < cnt; j++) {
            uint2 v = tr[(int)s_idx[j] * 256 + tid];
            acc4h(v, a0, a1, a2, a3);
        }
        const float s = LR_LTP_F / (float)BATCH;
        float4 w4 = reinterpret_cast<const float4*>(W)[col * (N_IN / 4) + tid];
        float4 r;
        r.x = s * (1.f - w4.x) * a0;
        r.y = s * (1.f - w4.y) * a1;
        r.z = s * (1.f - w4.z) * a2;
        r.w = s * (1.f - w4.w) * a3;
        reinterpret_cast<float4*>(dw)[col * (N_IN / 4) + tid] = r;
    } else {
        // rows of g_post_trh: 512 halves = 256 half2; thread covers o = 2t,2t+1
        const __half2* tr = reinterpret_cast<const __half2*>(g_post_trh);
        float a0 = 0.f, a1 = 0.f;
        int j = 0;
        for (; j + 4 <= cnt; j += 4) {
            __half2 v0 = tr[(int)s_idx[j + 0] * 256 + tid];
            __half2 v1 = tr[(int)s_idx[j + 1] * 256 + tid];
            __half2 v2 = tr[(int)s_idx[j + 2] * 256 + tid];
            __half2 v3 = tr[(int)s_idx[j + 3] * 256 + tid];
            float2 f;
            f = __half22float2(v0); a0 += f.x; a1 += f.y;
            f = __half22float2(v1); a0 += f.x; a1 += f.y;
            f = __half22float2(v2); a0 += f.x; a1 += f.y;
            f = __half22float2(v3); a0 += f.x; a1 += f.y;
        }
        for (; j < cnt; j++) {
            float2 f = __half22float2(tr[(int)s_idx[j] * 256 + tid]);
            a0 += f.x; a1 += f.y;
        }
        float2 r; r.x = a0; r.y = a1;
        reinterpret_cast<float2*>(g_bt)[col * (N_OUT / 2) + tid] = r;
    }
}

// ---------------------------------------------------------------------------
// Kernel C: dw[o,i] += (LR_LTD/B) * W[o,i] * BT[i,o]  (smem-transpose tiles)
// ---------------------------------------------------------------------------
__global__ void __launch_bounds__(256) combine_kernel(
    const float* __restrict__ W, float* __restrict__ dw)
{
    __shared__ float s[32][33];
    const int i0 = blockIdx.x * 32, o0 = blockIdx.y * 32;
    const int tx = threadIdx.x, ty = threadIdx.y;
    #pragma unroll
    for (int q = 0; q < 4; q++)
        s[ty + 8 * q][tx] = g_bt[(size_t)(i0 + ty + 8 * q) * N_OUT + o0 + tx];
    __syncthreads();
    const float c = LR_LTD_F / (float)BATCH;
    #pragma unroll
    for (int q = 0; q < 4; q++) {
        int o = o0 + ty + 8 * q;
        int i = i0 + tx;
        size_t p = (size_t)o * N_IN + i;
        dw[p] += c * W[p] * s[tx][ty + 8 * q];
    }
}

// ---------------------------------------------------------------------------
extern "C" void kernel_launch(void* const* d_in, const int* in_sizes, int n_in,
                              void* d_out, int out_size)
{
    const float* W        = (const float*)d_in[0];
    const float* pre_s    = (const float*)d_in[1];
    const float* post_s   = (const float*)d_in[2];
    const float* pre_tr0  = (const float*)d_in[3];
    const float* post_tr0 = (const float*)d_in[4];
    float* out = (float*)d_out;
    (void)in_sizes; (void)n_in; (void)out_size;

    prep_kernel<<<TRACE_CTAS + COMPACT_CTAS, 256>>>(
        pre_s, post_s, pre_tr0, post_tr0, out);
    gather_kernel<<<N_OUT + N_IN, 256>>>(W, out);
    combine_kernel<<<dim3(N_IN / 32, N_OUT / 32), dim3(32, 8)>>>(W, out);
}